// round 5
// baseline (speedup 1.0000x reference)
#include <cuda_runtime.h>
#include <math.h>

// Problem constants (fixed shapes from reference setup_inputs)
#define NB   8
#define ND   768
#define NCH  3
#define NMIX 5
#define NH   10
#define NS   10

#define PI2f      6.2831853071795864769f
#define LOG2Ef    1.4426950408889634074f
#define ZITTERf   1e-4f
#define GEPSf     1e-20f

#define T_TILES  24          // ND/32
#define NPAIR    300         // 24*25/2 upper-tri tile pairs
#define NSLOT    24          // one slot per partner tile

// Scratch (device globals: allocation is forbidden)
__device__ float g_featp[NSLOT][NB * ND * NCH * NMIX];  // exclusive partial features
__device__ float g_hpart[NB][T_TILES][NCH * NH];        // k2a partial relu-sums
__device__ float g_w[NB * NCH * NMIX];                  // mixture weights

// ---------------------------------------------------------------------------
// Kernel 1: feat[b,i,c,m] = sum_j K_m(x_i-x_j) * y_j, symmetric pair-blocks.
// One block = one upper-tri 32x32 tile-pair (ti <= tj). Uniform work.
//   i-side: rows of ti += K * y_j  -> slot tj  (warp shfl reduce)
//   j-side: rows of tj += K * y_i  -> slot ti  (cross-warp shared reduce),
//           skipped for diagonal pairs (i-side already covers full tile).
// Every (tile t, slot s) pair has exactly one writer -> no memset, no atomics.
// grid (300, NB*NCH), block (32,8).
// ---------------------------------------------------------------------------
__global__ __launch_bounds__(256) void k1_feature_pair(
    const float* __restrict__ xc, const float* __restrict__ yc,
    const float* __restrict__ mu, const float* __restrict__ inv_std)
{
    // decode upper-tri pair (ti <= tj)
    int p = blockIdx.x;
    int ti = 0, rem = T_TILES;
    while (p >= rem) { p -= rem; ++ti; --rem; }
    const int tj = ti + p;

    const int bc = blockIdx.y;
    const int b = bc / NCH, c = bc % NCH;

    const int tx = threadIdx.x;               // lane = j within tile
    const int ty = threadIdx.y;               // warp id (i sub-row)
    const int tid = ty * 32 + tx;

    __shared__ float sxi[32], syi[32];
    __shared__ float sxj[32], syj[32];
    __shared__ float sj[8][160];

    if (tid < 32)       sxi[tid]      = xc[(b * ND + ti * 32 + tid) * NCH + c];
    else if (tid < 64)  syi[tid - 64 + 32] = 0.f; // placeholder never used
    if (tid >= 32 && tid < 64)  syi[tid - 32] = yc[(b * ND + ti * 32 + (tid - 32)) * NCH + c];
    if (tid >= 64 && tid < 96)  sxj[tid - 64] = xc[(b * ND + tj * 32 + (tid - 64)) * NCH + c];
    if (tid >= 96 && tid < 128) syj[tid - 96] = yc[(b * ND + tj * 32 + (tid - 96)) * NCH + c];
    __syncthreads();

    float nA2[NMIX], wm[NMIX];
#pragma unroll
    for (int m = 0; m < NMIX; ++m) {
        float s = __ldg(&inv_std[m]);
        nA2[m] = -0.5f * PI2f * PI2f * s * s * LOG2Ef;   // exp2 domain
        wm[m]  = PI2f * __ldg(&mu[m]);
    }

    float xir[4], yir[4];
#pragma unroll
    for (int r = 0; r < 4; ++r) { xir[r] = sxi[ty + 8 * r]; yir[r] = syi[ty + 8 * r]; }

    const float xj = sxj[tx];
    const float yj = syj[tx];

    float acc_i[4][NMIX];
    float accj[NMIX] = {0.f, 0.f, 0.f, 0.f, 0.f};
#pragma unroll
    for (int r = 0; r < 4; ++r)
#pragma unroll
        for (int m = 0; m < NMIX; ++m) acc_i[r][m] = 0.f;

#pragma unroll
    for (int r = 0; r < 4; ++r) {
        float d  = xir[r] - xj;
        float d2 = d * d;
#pragma unroll
        for (int m = 0; m < NMIX; ++m) {
            float e  = exp2f(nA2[m] * d2);
            float cs = __cosf(wm[m] * d);
            float kv = e * cs;
            acc_i[r][m] = fmaf(kv, yj, acc_i[r][m]);
            accj[m]     = fmaf(kv, yir[r], accj[m]);
        }
    }

    // j-side -> slot ti (rows of tj), skip on diagonal
    if (ti != tj) {
#pragma unroll
        for (int m = 0; m < NMIX; ++m) sj[ty][tx * 5 + m] = accj[m];
        __syncthreads();
        if (tid < 160) {
            float s = 0.f;
#pragma unroll
            for (int w = 0; w < 8; ++w) s += sj[w][tid];
            int jl = tid / 5, m = tid % 5;
            g_featp[ti][((b * ND + tj * 32 + jl) * NCH + c) * NMIX + m] = s;
        }
    }

    // i-side -> slot tj (rows of ti): lane reduce over 32 j's
#pragma unroll
    for (int r = 0; r < 4; ++r) {
        int base = ((b * ND + ti * 32 + ty + 8 * r) * NCH + c) * NMIX;
#pragma unroll
        for (int m = 0; m < NMIX; ++m) {
            float v = acc_i[r][m];
            v += __shfl_down_sync(0xffffffffu, v, 16);
            v += __shfl_down_sync(0xffffffffu, v, 8);
            v += __shfl_down_sync(0xffffffffu, v, 4);
            v += __shfl_down_sync(0xffffffffu, v, 2);
            v += __shfl_down_sync(0xffffffffu, v, 1);
            if (tx == 0) g_featp[tj][base + m] = v;
        }
    }
}

// ---------------------------------------------------------------------------
// Kernel 2a: partial relu-hidden sums per 32-row tile. Reads all 24 slots.
// grid (24, NB), block 128 (96 active).
// ---------------------------------------------------------------------------
__global__ __launch_bounds__(128) void k2a_hidden(
    const float* __restrict__ yc,
    const float* __restrict__ W1, const float* __restrict__ b1)
{
    const int blk = blockIdx.x;               // row tile
    const int b   = blockIdx.y;
    const int t   = threadIdx.x;

    __shared__ float spart[96][NH];

    if (t < 96) {
        const int i = blk * 32 + t / 3;
        const int c = t % 3;
        const int base = ((b * ND + i) * NCH + c) * NMIX;

        float fs[NMIX] = {0.f, 0.f, 0.f, 0.f, 0.f};
#pragma unroll 4
        for (int s = 0; s < NSLOT; ++s) {
#pragma unroll
            for (int m = 0; m < NMIX; ++m) fs[m] += g_featp[s][base + m];
        }
        const float y = __ldg(&yc[(b * ND + i) * NCH + c]);
#pragma unroll
        for (int m = 0; m < NMIX; ++m) fs[m] += ZITTERf * y;

#pragma unroll
        for (int k = 0; k < NH; ++k) {
            float h = __ldg(&b1[k]);
#pragma unroll
            for (int m = 0; m < NMIX; ++m)
                h = fmaf(fs[m], __ldg(&W1[k * (NMIX + 1) + m]), h);
            h = fmaf(y, __ldg(&W1[k * (NMIX + 1) + NMIX]), h);
            spart[t][k] = fmaxf(h, 0.f);
        }
    }
    __syncthreads();

    if (t < NCH * NH) {                       // t = c*10 + k
        const int c = t / NH, k = t % NH;
        float s = 0.f;
#pragma unroll
        for (int r = 0; r < 32; ++r) s += spart[r * 3 + c][k];
        g_hpart[b][blk][t] = s;
    }
}

// ---------------------------------------------------------------------------
// Kernel 2b: finish mean, MLP chain, Gumbel-softmax -> g_w. grid NB, block 32.
// ---------------------------------------------------------------------------
__global__ __launch_bounds__(32) void k2b_mlp_gumbel(
    const float* __restrict__ unif,
    const float* __restrict__ W2, const float* __restrict__ b2,
    const float* __restrict__ W3, const float* __restrict__ b3,
    const float* __restrict__ W4, const float* __restrict__ b4,
    const float* __restrict__ W5, const float* __restrict__ b5)
{
    const int b = blockIdx.x;
    const int tid = threadIdx.x;

    __shared__ float sflat[NCH * NH];
    __shared__ float sh2[NH], sh3[NH], sh4[NH];
    __shared__ float sll[NCH * NMIX];
    __shared__ float sg[NS * NCH][NMIX];

    if (tid < NCH * NH) {
        float s = 0.f;
        for (int p = 0; p < T_TILES; ++p) s += g_hpart[b][p][tid];
        sflat[tid] = s * (1.0f / (float)ND);
    }
    __syncthreads();
    if (tid < NH) {
        float a = __ldg(&b2[tid]);
        for (int t = 0; t < NCH * NH; ++t) a = fmaf(sflat[t], __ldg(&W2[tid * NCH * NH + t]), a);
        sh2[tid] = fmaxf(a, 0.f);
    }
    __syncthreads();
    if (tid < NH) {
        float a = __ldg(&b3[tid]);
        for (int t = 0; t < NH; ++t) a = fmaf(sh2[t], __ldg(&W3[tid * NH + t]), a);
        sh3[tid] = fmaxf(a, 0.f);
    }
    __syncthreads();
    if (tid < NH) {
        float a = __ldg(&b4[tid]);
        for (int t = 0; t < NH; ++t) a = fmaf(sh3[t], __ldg(&W4[tid * NH + t]), a);
        sh4[tid] = fmaxf(a, 0.f);
    }
    __syncthreads();
    if (tid < NCH * NMIX) {
        float a = __ldg(&b5[tid]);
        for (int k = 0; k < NH; ++k) a = fmaf(sh4[k], __ldg(&W5[tid * NH + k]), a);
        sll[tid] = a;
    }
    __syncthreads();

    if (tid < NS * NCH) {                     // tid = s*3 + c
        const int s = tid / NCH, c = tid % NCH;
        float z[NMIX], zm = -1e30f;
#pragma unroll
        for (int m = 0; m < NMIX; ++m) {
            float u = __ldg(&unif[((b * NS + s) * NCH + c) * NMIX + m]);
            float gb = -__logf(-__logf(u + GEPSf));
            z[m] = (gb + sll[c * NMIX + m]) * 10.0f;   // /TEMP, TEMP=0.1
            zm = fmaxf(zm, z[m]);
        }
        float e[NMIX], sum = 0.f;
#pragma unroll
        for (int m = 0; m < NMIX; ++m) { e[m] = __expf(z[m] - zm); sum += e[m]; }
        float inv = 1.0f / (sum * (float)NS);          // fold mean over ns
#pragma unroll
        for (int m = 0; m < NMIX; ++m) sg[tid][m] = e[m] * inv;
    }
    __syncthreads();
    if (tid < NCH * NMIX) {                   // tid = c*5 + m
        const int c = tid / NMIX, m = tid % NMIX;
        float w = 0.f;
#pragma unroll
        for (int s = 0; s < NS; ++s) w += sg[s * NCH + c][m];
        g_w[b * NCH * NMIX + tid] = w;
    }
}

// ---------------------------------------------------------------------------
// Kernel 3 (R2 structure, reverted): out[b,i,j,c] = sum_m w*K_m(d) + diag
// Upper-triangle pair decode, mirror via padded shared transpose.
// grid (300, NB), block (32, 8).
// ---------------------------------------------------------------------------
#define TPAD 99   // 32*3 padded -> stride 3 mod 32 conflict-free

__global__ __launch_bounds__(256) void k3_weighted(
    const float* __restrict__ xc, const float* __restrict__ mu,
    const float* __restrict__ inv_std, const float* __restrict__ likerr,
    float* __restrict__ out)
{
    // decode upper-tri pair (ti <= tj)
    int p = blockIdx.x;
    int ti = 0, rem = T_TILES;
    while (p >= rem) { p -= rem; ++ti; --rem; }
    const int tj = ti + p;

    const int b = blockIdx.y;
    const int i0 = ti * 32, j0 = tj * 32;
    const int tx = threadIdx.x, ty = threadIdx.y;
    const int tid = ty * 32 + tx;

    __shared__ float sxi[32 * NCH], sxj[32 * NCH];
    __shared__ float swv[NCH * NMIX], snA2[NMIX], swm[NMIX], sdiag[NCH];
    __shared__ float tile[32][TPAD];

    if (tid < 96)       sxi[tid]      = xc[(b * ND + i0) * NCH + tid];
    else if (tid < 192) sxj[tid - 96] = xc[(b * ND + j0) * NCH + (tid - 96)];
    if (tid < NCH * NMIX) swv[tid] = g_w[b * NCH * NMIX + tid];
    if (tid < NMIX) {
        float s = inv_std[tid];
        snA2[tid] = -0.5f * PI2f * PI2f * s * s * LOG2Ef;   // exp2 domain
        swm[tid]  = PI2f * mu[tid];
    }
    if (tid < NCH) {
        float l = fminf(fmaxf(likerr[tid], 0.1f), 1.0f);
        sdiag[tid] = ZITTERf + l * l;
    }
    __syncthreads();

#pragma unroll
    for (int r = 0; r < 4; ++r) {
        int tr = ty + 8 * r;
        int i = i0 + tr;
        int j = j0 + tx;
        int base = ((b * ND + i) * ND + j) * NCH;
#pragma unroll
        for (int c = 0; c < NCH; ++c) {
            float d  = sxi[tr * NCH + c] - sxj[tx * NCH + c];
            float d2 = d * d;
            float acc = 0.f;
#pragma unroll
            for (int m = 0; m < NMIX; ++m) {
                float e  = exp2f(snA2[m] * d2);
                float cs = __cosf(swm[m] * d);
                acc = fmaf(swv[c * NMIX + m], e * cs, acc);
            }
            if (i == j) acc += sdiag[c];
            out[base + c] = acc;
            tile[tr][tx * NCH + c] = acc;
        }
    }

    if (ti != tj) {
        __syncthreads();
#pragma unroll
        for (int r = 0; r < 4; ++r) {
            int jj = ty + 8 * r;
            int base = ((b * ND + j0 + jj) * ND + (i0 + tx)) * NCH;
#pragma unroll
            for (int c = 0; c < NCH; ++c)
                out[base + c] = tile[tx][jj * NCH + c];
        }
    }
}

// ---------------------------------------------------------------------------
// Launch. Input order: xc, yc, mu, inv_std, likerr, unif, W1..b5
// ---------------------------------------------------------------------------
extern "C" void kernel_launch(void* const* d_in, const int* in_sizes, int n_in,
                              void* d_out, int out_size)
{
    const float* xc      = (const float*)d_in[0];
    const float* yc      = (const float*)d_in[1];
    const float* mu      = (const float*)d_in[2];
    const float* inv_std = (const float*)d_in[3];
    const float* likerr  = (const float*)d_in[4];
    const float* unif    = (const float*)d_in[5];
    const float* W1 = (const float*)d_in[6];  const float* b1 = (const float*)d_in[7];
    const float* W2 = (const float*)d_in[8];  const float* b2 = (const float*)d_in[9];
    const float* W3 = (const float*)d_in[10]; const float* b3 = (const float*)d_in[11];
    const float* W4 = (const float*)d_in[12]; const float* b4 = (const float*)d_in[13];
    const float* W5 = (const float*)d_in[14]; const float* b5 = (const float*)d_in[15];
    float* out = (float*)d_out;

    dim3 g1(NPAIR, NB * NCH);
    dim3 t1(32, 8);
    k1_feature_pair<<<g1, t1>>>(xc, yc, mu, inv_std);

    dim3 g2a(T_TILES, NB);
    k2a_hidden<<<g2a, 128>>>(yc, W1, b1);

    k2b_mlp_gumbel<<<NB, 32>>>(unif, W2, b2, W3, b3, W4, b4, W5, b5);

    dim3 g3(NPAIR, NB);
    dim3 t3(32, 8);
    k3_weighted<<<g3, t3>>>(xc, mu, inv_std, likerr, out);
}

// round 6
// speedup vs baseline: 1.3127x; 1.3127x over previous
#include <cuda_runtime.h>
#include <math.h>

// Problem constants (fixed shapes from reference setup_inputs)
#define NB   8
#define ND   768
#define NCH  3
#define NMIX 5
#define NH   10
#define NS   10

#define PI2f      6.2831853071795864769f
#define LOG2Ef    1.4426950408889634074f
#define ZITTERf   1e-4f
#define GEPSf     1e-20f

#define T_TILES  24          // ND/32
#define NPAIR    300         // 24*25/2 upper-tri tile pairs (k3)
#define NSLOT    24          // slot s of tile t: s<t j-side, s==t i-side

// Scratch (device globals: allocation is forbidden)
__device__ float g_featp[NSLOT][NB * ND * NCH * NMIX];  // exclusive partial features
__device__ float g_hpart[NB][T_TILES][NCH * NH];        // k2a partial relu-sums
__device__ float g_w[NB * NCH * NMIX];                  // mixture weights

// ---------------------------------------------------------------------------
// Kernel 1: balanced double-strip. Block owns row tiles ti1=bx and ti2=23-bx;
// strip(t) covers tiles tj in [t, 24) -> 25 tiles total per block (uniform).
//   i-side: rows of t accumulate in regs across whole strip -> slot t
//   j-side: rows of tj (tj>t) reduced via shared per tile -> slot t
// grid (12, NB*NCH), block (32,8). 288 blocks = one full chip wave.
// ---------------------------------------------------------------------------
__global__ __launch_bounds__(256) void k1_feature_bal(
    const float* __restrict__ xc, const float* __restrict__ yc,
    const float* __restrict__ mu, const float* __restrict__ inv_std)
{
    const int ti1 = blockIdx.x;               // 0..11
    const int ti2 = T_TILES - 1 - ti1;        // 23..12
    const int bc = blockIdx.y;
    const int b = bc / NCH, c = bc % NCH;

    const int tx = threadIdx.x;               // lane = j within tile
    const int ty = threadIdx.y;               // warp id (i sub-row)
    const int tid = ty * 32 + tx;

    __shared__ float sj[2][8][160];

    float nA2[NMIX], wm[NMIX];
#pragma unroll
    for (int m = 0; m < NMIX; ++m) {
        float s = __ldg(&inv_std[m]);
        nA2[m] = -0.5f * PI2f * PI2f * s * s * LOG2Ef;   // exp2 domain
        wm[m]  = PI2f * __ldg(&mu[m]);
    }

    // row data for both strips (4 rows per thread each)
    float xi1[4], yi1[4], xi2[4], yi2[4];
#pragma unroll
    for (int r = 0; r < 4; ++r) {
        int i1 = ti1 * 32 + ty + 8 * r;
        int i2 = ti2 * 32 + ty + 8 * r;
        xi1[r] = __ldg(&xc[(b * ND + i1) * NCH + c]);
        yi1[r] = __ldg(&yc[(b * ND + i1) * NCH + c]);
        xi2[r] = __ldg(&xc[(b * ND + i2) * NCH + c]);
        yi2[r] = __ldg(&yc[(b * ND + i2) * NCH + c]);
    }

    float acc1[4][NMIX], acc2[4][NMIX];
#pragma unroll
    for (int r = 0; r < 4; ++r)
#pragma unroll
        for (int m = 0; m < NMIX; ++m) { acc1[r][m] = 0.f; acc2[r][m] = 0.f; }

    int buf = 0;

    // ---- strip A: row tile ti1, tj = ti1..23 ----
    for (int tj = ti1; tj < T_TILES; ++tj) {
        const float xj = __ldg(&xc[(b * ND + tj * 32 + tx) * NCH + c]);
        const float yj = __ldg(&yc[(b * ND + tj * 32 + tx) * NCH + c]);
        float accjp[NMIX] = {0.f, 0.f, 0.f, 0.f, 0.f};
#pragma unroll
        for (int r = 0; r < 4; ++r) {
            float d  = xi1[r] - xj;
            float d2 = d * d;
#pragma unroll
            for (int m = 0; m < NMIX; ++m) {
                float e  = exp2f(nA2[m] * d2);
                float cs = __cosf(wm[m] * d);
                float kv = e * cs;
                acc1[r][m] = fmaf(kv, yj, acc1[r][m]);
                accjp[m]   = fmaf(kv, yi1[r], accjp[m]);
            }
        }
        if (tj != ti1) {                      // j-side -> slot ti1, rows of tj
#pragma unroll
            for (int m = 0; m < NMIX; ++m) sj[buf][ty][tx * 5 + m] = accjp[m];
            __syncthreads();
            if (tid < 160) {
                float s = 0.f;
#pragma unroll
                for (int w = 0; w < 8; ++w) s += sj[buf][w][tid];
                g_featp[ti1][((b * ND + tj * 32 + tid / 5) * NCH + c) * NMIX + tid % 5] = s;
            }
            buf ^= 1;
        }
    }

    // ---- strip B: row tile ti2, tj = ti2..23 ----
    for (int tj = ti2; tj < T_TILES; ++tj) {
        const float xj = __ldg(&xc[(b * ND + tj * 32 + tx) * NCH + c]);
        const float yj = __ldg(&yc[(b * ND + tj * 32 + tx) * NCH + c]);
        float accjp[NMIX] = {0.f, 0.f, 0.f, 0.f, 0.f};
#pragma unroll
        for (int r = 0; r < 4; ++r) {
            float d  = xi2[r] - xj;
            float d2 = d * d;
#pragma unroll
            for (int m = 0; m < NMIX; ++m) {
                float e  = exp2f(nA2[m] * d2);
                float cs = __cosf(wm[m] * d);
                float kv = e * cs;
                acc2[r][m] = fmaf(kv, yj, acc2[r][m]);
                accjp[m]   = fmaf(kv, yi2[r], accjp[m]);
            }
        }
        if (tj != ti2) {                      // j-side -> slot ti2, rows of tj
#pragma unroll
            for (int m = 0; m < NMIX; ++m) sj[buf][ty][tx * 5 + m] = accjp[m];
            __syncthreads();
            if (tid < 160) {
                float s = 0.f;
#pragma unroll
                for (int w = 0; w < 8; ++w) s += sj[buf][w][tid];
                g_featp[ti2][((b * ND + tj * 32 + tid / 5) * NCH + c) * NMIX + tid % 5] = s;
            }
            buf ^= 1;
        }
    }

    // ---- i-side epilogues: lane reduce over 32 j's, once per strip ----
#pragma unroll
    for (int r = 0; r < 4; ++r) {
        int base1 = ((b * ND + ti1 * 32 + ty + 8 * r) * NCH + c) * NMIX;
        int base2 = ((b * ND + ti2 * 32 + ty + 8 * r) * NCH + c) * NMIX;
#pragma unroll
        for (int m = 0; m < NMIX; ++m) {
            float v = acc1[r][m];
            v += __shfl_down_sync(0xffffffffu, v, 16);
            v += __shfl_down_sync(0xffffffffu, v, 8);
            v += __shfl_down_sync(0xffffffffu, v, 4);
            v += __shfl_down_sync(0xffffffffu, v, 2);
            v += __shfl_down_sync(0xffffffffu, v, 1);
            if (tx == 0) g_featp[ti1][base1 + m] = v;
            float u = acc2[r][m];
            u += __shfl_down_sync(0xffffffffu, u, 16);
            u += __shfl_down_sync(0xffffffffu, u, 8);
            u += __shfl_down_sync(0xffffffffu, u, 4);
            u += __shfl_down_sync(0xffffffffu, u, 2);
            u += __shfl_down_sync(0xffffffffu, u, 1);
            if (tx == 0) g_featp[ti2][base2 + m] = u;
        }
    }
}

// ---------------------------------------------------------------------------
// Kernel 2a: partial relu-hidden sums per 32-row tile.
// Row tile t reads slots 0..t inclusive (exactly the populated ones).
// grid (24, NB), block 128 (96 active).
// ---------------------------------------------------------------------------
__global__ __launch_bounds__(128) void k2a_hidden(
    const float* __restrict__ yc,
    const float* __restrict__ W1, const float* __restrict__ b1)
{
    const int blk = blockIdx.x;               // row tile
    const int b   = blockIdx.y;
    const int t   = threadIdx.x;

    __shared__ float spart[96][NH];

    if (t < 96) {
        const int i = blk * 32 + t / 3;
        const int c = t % 3;
        const int base = ((b * ND + i) * NCH + c) * NMIX;

        float fs[NMIX] = {0.f, 0.f, 0.f, 0.f, 0.f};
        for (int s = 0; s <= blk; ++s) {
#pragma unroll
            for (int m = 0; m < NMIX; ++m) fs[m] += g_featp[s][base + m];
        }
        const float y = __ldg(&yc[(b * ND + i) * NCH + c]);
#pragma unroll
        for (int m = 0; m < NMIX; ++m) fs[m] += ZITTERf * y;

#pragma unroll
        for (int k = 0; k < NH; ++k) {
            float h = __ldg(&b1[k]);
#pragma unroll
            for (int m = 0; m < NMIX; ++m)
                h = fmaf(fs[m], __ldg(&W1[k * (NMIX + 1) + m]), h);
            h = fmaf(y, __ldg(&W1[k * (NMIX + 1) + NMIX]), h);
            spart[t][k] = fmaxf(h, 0.f);
        }
    }
    __syncthreads();

    if (t < NCH * NH) {                       // t = c*10 + k
        const int c = t / NH, k = t % NH;
        float s = 0.f;
#pragma unroll
        for (int r = 0; r < 32; ++r) s += spart[r * 3 + c][k];
        g_hpart[b][blk][t] = s;
    }
}

// ---------------------------------------------------------------------------
// Kernel 2b: finish mean, MLP chain, Gumbel-softmax -> g_w. grid NB, block 32.
// ---------------------------------------------------------------------------
__global__ __launch_bounds__(32) void k2b_mlp_gumbel(
    const float* __restrict__ unif,
    const float* __restrict__ W2, const float* __restrict__ b2,
    const float* __restrict__ W3, const float* __restrict__ b3,
    const float* __restrict__ W4, const float* __restrict__ b4,
    const float* __restrict__ W5, const float* __restrict__ b5)
{
    const int b = blockIdx.x;
    const int tid = threadIdx.x;

    __shared__ float sflat[NCH * NH];
    __shared__ float sh2[NH], sh3[NH], sh4[NH];
    __shared__ float sll[NCH * NMIX];
    __shared__ float sg[NS * NCH][NMIX];

    if (tid < NCH * NH) {
        float s = 0.f;
        for (int p = 0; p < T_TILES; ++p) s += g_hpart[b][p][tid];
        sflat[tid] = s * (1.0f / (float)ND);
    }
    __syncthreads();
    if (tid < NH) {
        float a = __ldg(&b2[tid]);
        for (int t = 0; t < NCH * NH; ++t) a = fmaf(sflat[t], __ldg(&W2[tid * NCH * NH + t]), a);
        sh2[tid] = fmaxf(a, 0.f);
    }
    __syncthreads();
    if (tid < NH) {
        float a = __ldg(&b3[tid]);
        for (int t = 0; t < NH; ++t) a = fmaf(sh2[t], __ldg(&W3[tid * NH + t]), a);
        sh3[tid] = fmaxf(a, 0.f);
    }
    __syncthreads();
    if (tid < NH) {
        float a = __ldg(&b4[tid]);
        for (int t = 0; t < NH; ++t) a = fmaf(sh3[t], __ldg(&W4[tid * NH + t]), a);
        sh4[tid] = fmaxf(a, 0.f);
    }
    __syncthreads();
    if (tid < NCH * NMIX) {
        float a = __ldg(&b5[tid]);
        for (int k = 0; k < NH; ++k) a = fmaf(sh4[k], __ldg(&W5[tid * NH + k]), a);
        sll[tid] = a;
    }
    __syncthreads();

    if (tid < NS * NCH) {                     // tid = s*3 + c
        const int s = tid / NCH, c = tid % NCH;
        float z[NMIX], zm = -1e30f;
#pragma unroll
        for (int m = 0; m < NMIX; ++m) {
            float u = __ldg(&unif[((b * NS + s) * NCH + c) * NMIX + m]);
            float gb = -__logf(-__logf(u + GEPSf));
            z[m] = (gb + sll[c * NMIX + m]) * 10.0f;   // /TEMP, TEMP=0.1
            zm = fmaxf(zm, z[m]);
        }
        float e[NMIX], sum = 0.f;
#pragma unroll
        for (int m = 0; m < NMIX; ++m) { e[m] = __expf(z[m] - zm); sum += e[m]; }
        float inv = 1.0f / (sum * (float)NS);          // fold mean over ns
#pragma unroll
        for (int m = 0; m < NMIX; ++m) sg[tid][m] = e[m] * inv;
    }
    __syncthreads();
    if (tid < NCH * NMIX) {                   // tid = c*5 + m
        const int c = tid / NMIX, m = tid % NMIX;
        float w = 0.f;
#pragma unroll
        for (int s = 0; s < NS; ++s) w += sg[s * NCH + c][m];
        g_w[b * NCH * NMIX + tid] = w;
    }
}

// ---------------------------------------------------------------------------
// Kernel 3 (unchanged, best known): out[b,i,j,c] = sum_m w*K_m(d) + diag
// Upper-triangle pair decode, mirror via padded shared transpose.
// grid (300, NB), block (32, 8).
// ---------------------------------------------------------------------------
#define TPAD 99   // 32*3 padded -> stride 3 mod 32 conflict-free

__global__ __launch_bounds__(256) void k3_weighted(
    const float* __restrict__ xc, const float* __restrict__ mu,
    const float* __restrict__ inv_std, const float* __restrict__ likerr,
    float* __restrict__ out)
{
    // decode upper-tri pair (ti <= tj)
    int p = blockIdx.x;
    int ti = 0, rem = T_TILES;
    while (p >= rem) { p -= rem; ++ti; --rem; }
    const int tj = ti + p;

    const int b = blockIdx.y;
    const int i0 = ti * 32, j0 = tj * 32;
    const int tx = threadIdx.x, ty = threadIdx.y;
    const int tid = ty * 32 + tx;

    __shared__ float sxi[32 * NCH], sxj[32 * NCH];
    __shared__ float swv[NCH * NMIX], snA2[NMIX], swm[NMIX], sdiag[NCH];
    __shared__ float tile[32][TPAD];

    if (tid < 96)       sxi[tid]      = xc[(b * ND + i0) * NCH + tid];
    else if (tid < 192) sxj[tid - 96] = xc[(b * ND + j0) * NCH + (tid - 96)];
    if (tid < NCH * NMIX) swv[tid] = g_w[b * NCH * NMIX + tid];
    if (tid < NMIX) {
        float s = inv_std[tid];
        snA2[tid] = -0.5f * PI2f * PI2f * s * s * LOG2Ef;   // exp2 domain
        swm[tid]  = PI2f * mu[tid];
    }
    if (tid < NCH) {
        float l = fminf(fmaxf(likerr[tid], 0.1f), 1.0f);
        sdiag[tid] = ZITTERf + l * l;
    }
    __syncthreads();

#pragma unroll
    for (int r = 0; r < 4; ++r) {
        int tr = ty + 8 * r;
        int i = i0 + tr;
        int j = j0 + tx;
        int base = ((b * ND + i) * ND + j) * NCH;
#pragma unroll
        for (int c = 0; c < NCH; ++c) {
            float d  = sxi[tr * NCH + c] - sxj[tx * NCH + c];
            float d2 = d * d;
            float acc = 0.f;
#pragma unroll
            for (int m = 0; m < NMIX; ++m) {
                float e  = exp2f(snA2[m] * d2);
                float cs = __cosf(swm[m] * d);
                acc = fmaf(swv[c * NMIX + m], e * cs, acc);
            }
            if (i == j) acc += sdiag[c];
            out[base + c] = acc;
            tile[tr][tx * NCH + c] = acc;
        }
    }

    if (ti != tj) {
        __syncthreads();
#pragma unroll
        for (int r = 0; r < 4; ++r) {
            int jj = ty + 8 * r;
            int base = ((b * ND + j0 + jj) * ND + (i0 + tx)) * NCH;
#pragma unroll
            for (int c = 0; c < NCH; ++c)
                out[base + c] = tile[tx][jj * NCH + c];
        }
    }
}

// ---------------------------------------------------------------------------
// Launch. Input order: xc, yc, mu, inv_std, likerr, unif, W1..b5
// ---------------------------------------------------------------------------
extern "C" void kernel_launch(void* const* d_in, const int* in_sizes, int n_in,
                              void* d_out, int out_size)
{
    const float* xc      = (const float*)d_in[0];
    const float* yc      = (const float*)d_in[1];
    const float* mu      = (const float*)d_in[2];
    const float* inv_std = (const float*)d_in[3];
    const float* likerr  = (const float*)d_in[4];
    const float* unif    = (const float*)d_in[5];
    const float* W1 = (const float*)d_in[6];  const float* b1 = (const float*)d_in[7];
    const float* W2 = (const float*)d_in[8];  const float* b2 = (const float*)d_in[9];
    const float* W3 = (const float*)d_in[10]; const float* b3 = (const float*)d_in[11];
    const float* W4 = (const float*)d_in[12]; const float* b4 = (const float*)d_in[13];
    const float* W5 = (const float*)d_in[14]; const float* b5 = (const float*)d_in[15];
    float* out = (float*)d_out;

    dim3 g1(T_TILES / 2, NB * NCH);
    dim3 t1(32, 8);
    k1_feature_bal<<<g1, t1>>>(xc, yc, mu, inv_std);

    dim3 g2a(T_TILES, NB);
    k2a_hidden<<<g2a, 128>>>(yc, W1, b1);

    k2b_mlp_gumbel<<<NB, 32>>>(unif, W2, b2, W3, b3, W4, b4, W5, b5);

    dim3 g3(NPAIR, NB);
    dim3 t3(32, 8);
    k3_weighted<<<g3, t3>>>(xc, mu, inv_std, likerr, out);
}